// round 9
// baseline (speedup 1.0000x reference)
#include <cuda_runtime.h>

#define NC    21
#define HW    (512 * 512)
#define NB    16
#define BHW   (NB * HW)
#define NBINS (NC * NC)
#define QPI   (HW / 4)          /* quads (float4) per image plane = 65536 */

// Confusion-matrix scratch. Zero at module load (BSS); loss_kernel re-zeroes it
// after consuming it, so every launch (incl. graph replays) starts clean.
__device__ unsigned int g_conf[NBINS];

// 2048 blocks x 256 threads = 524288 threads; each handles exactly TWO adjacent
// quads (8 pixels) -> 2^20 quads, one shot, no loop raggedness.
#define GRID 2048

__global__ void __launch_bounds__(256)
hist_kernel(const float* __restrict__ logits, const int* __restrict__ target) {
    __shared__ unsigned int s_conf[NBINS];
    for (int i = threadIdx.x; i < NBINS; i += 256) s_conf[i] = 0u;
    __syncthreads();

    int g  = blockIdx.x * 256 + threadIdx.x;   // 0 .. 524287
    int q0 = g << 1;                            // even quad; q0,q0+1 same image
    int b  = q0 >> 16;                          // q0 / QPI
    int s  = (q0 - (b << 16)) << 2;             // pixel offset within image
    const float4* base =
        (const float4*)(logits + (size_t)b * NC * HW + s);

    // 8 pixels: two adjacent float4 per class -> 32B contiguous per thread.
    float4 v0 = __ldcs(base);
    float4 v1 = __ldcs(base + 1);
    float m0 = v0.x, m1 = v0.y, m2 = v0.z, m3 = v0.w;
    float m4 = v1.x, m5 = v1.y, m6 = v1.z, m7 = v1.w;
    int a0 = 0, a1 = 0, a2 = 0, a3 = 0, a4 = 0, a5 = 0, a6 = 0, a7 = 0;
    #pragma unroll
    for (int c = 1; c < NC; c++) {
        float4 u0 = __ldcs(base + (size_t)c * QPI);
        float4 u1 = __ldcs(base + (size_t)c * QPI + 1);
        if (u0.x > m0) { m0 = u0.x; a0 = c; }
        if (u0.y > m1) { m1 = u0.y; a1 = c; }
        if (u0.z > m2) { m2 = u0.z; a2 = c; }
        if (u0.w > m3) { m3 = u0.w; a3 = c; }
        if (u1.x > m4) { m4 = u1.x; a4 = c; }
        if (u1.y > m5) { m5 = u1.y; a5 = c; }
        if (u1.z > m6) { m6 = u1.z; a6 = c; }
        if (u1.w > m7) { m7 = u1.w; a7 = c; }
    }

    int p = g << 3;                              // first of 8 pixels
    int4 t0 = __ldcs((const int4*)(target + p));      // 16B-aligned
    int4 t1 = __ldcs((const int4*)(target + p + 4));
    atomicAdd(&s_conf[t0.x * NC + a0], 1u);
    atomicAdd(&s_conf[t0.y * NC + a1], 1u);
    atomicAdd(&s_conf[t0.z * NC + a2], 1u);
    atomicAdd(&s_conf[t0.w * NC + a3], 1u);
    atomicAdd(&s_conf[t1.x * NC + a4], 1u);
    atomicAdd(&s_conf[t1.y * NC + a5], 1u);
    atomicAdd(&s_conf[t1.z * NC + a6], 1u);
    atomicAdd(&s_conf[t1.w * NC + a7], 1u);

    __syncthreads();
    for (int i = threadIdx.x; i < NBINS; i += 256) {
        unsigned int v = s_conf[i];
        if (v) atomicAdd(&g_conf[i], v);
    }
}

__global__ void __launch_bounds__(512)
loss_kernel(float* __restrict__ out) {
    __shared__ unsigned int s_conf[NBINS];
    int i = threadIdx.x;

    // Snapshot the confusion matrix, then reset it for the next launch/replay.
    if (i < NBINS) s_conf[i] = g_conf[i];
    __syncthreads();
    if (i < NBINS) g_conf[i] = 0u;

    float acc = 0.0f;
    if (i < NC) {
        float tp = (float)s_conf[i * NC + i];
        float rowsum = 0.0f, colsum = 0.0f;
        #pragma unroll
        for (int j = 0; j < NC; j++) {
            rowsum += (float)s_conf[i * NC + j];
            colsum += (float)s_conf[j * NC + i];
        }
        float fp = rowsum - tp;
        float fn = colsum - tp;
        float tn = (float)BHW - tp - fp - fn;
        float sens = (tp + 1.0f) / (tp + fn + 1.0f);
        float spec = (tn + 1.0f) / (tn + fp + 1.0f);
        acc = 0.5f * sens + 0.5f * spec;
    }
    if (i < 32) {   // classes 0..20 all live in warp 0
        #pragma unroll
        for (int off = 16; off > 0; off >>= 1)
            acc += __shfl_down_sync(0xffffffffu, acc, off);
        if (i == 0) out[0] = 1.0f - acc / (float)NC;
    }
}

extern "C" void kernel_launch(void* const* d_in, const int* in_sizes, int n_in,
                              void* d_out, int out_size) {
    const float* logits = (const float*)d_in[0];
    const int* target   = (const int*)d_in[1];
    float* out = (float*)d_out;

    hist_kernel<<<GRID, 256>>>(logits, target);
    loss_kernel<<<1, 512>>>(out);
}

// round 11
// speedup vs baseline: 1.6126x; 1.6126x over previous
#include <cuda_runtime.h>

#define NC    21
#define HW    (512 * 512)
#define NB    16
#define BHW   (NB * HW)
#define NBINS (NC * NC)

// Confusion-matrix scratch. Zero at module load (BSS); loss_kernel re-zeroes it
// after consuming it, so every launch (incl. graph replays) starts clean.
__device__ unsigned int g_conf[NBINS];

// ---- hist_kernel: exact copy of the R3 configuration (fastest measured) ----
__global__ void __launch_bounds__(256)
hist_kernel(const float* __restrict__ logits, const int* __restrict__ target) {
    __shared__ unsigned int s_conf[NBINS];
    for (int i = threadIdx.x; i < NBINS; i += 256) s_conf[i] = 0u;
    __syncthreads();

    const int nquads = BHW / 4;  // 1,048,576 quads of 4 pixels
    for (int q = blockIdx.x * 256 + threadIdx.x; q < nquads;
         q += gridDim.x * 256) {
        int p = q << 2;                 // pixel index (multiple of 4, stays in same b)
        int b = p / HW;
        int s = p - b * HW;
        const float4* base =
            (const float4*)(logits + (size_t)b * NC * HW + s);

        float4 v = __ldg(base);
        float m0 = v.x, m1 = v.y, m2 = v.z, m3 = v.w;
        int a0 = 0, a1 = 0, a2 = 0, a3 = 0;
        #pragma unroll
        for (int c = 1; c < NC; c++) {
            float4 u = __ldg(base + (size_t)c * (HW / 4));
            if (u.x > m0) { m0 = u.x; a0 = c; }
            if (u.y > m1) { m1 = u.y; a1 = c; }
            if (u.z > m2) { m2 = u.z; a2 = c; }
            if (u.w > m3) { m3 = u.w; a3 = c; }
        }

        int4 t = *(const int4*)(target + p);   // 16B-aligned: p % 4 == 0
        atomicAdd(&s_conf[t.x * NC + a0], 1u);
        atomicAdd(&s_conf[t.y * NC + a1], 1u);
        atomicAdd(&s_conf[t.z * NC + a2], 1u);
        atomicAdd(&s_conf[t.w * NC + a3], 1u);
    }

    __syncthreads();
    for (int i = threadIdx.x; i < NBINS; i += 256) {
        unsigned int v = s_conf[i];
        if (v) atomicAdd(&g_conf[i], v);
    }
}

// ---- loss_kernel: consumes g_conf, writes scalar, resets state ----
__global__ void __launch_bounds__(512)
loss_kernel(float* __restrict__ out) {
    __shared__ unsigned int s_conf[NBINS];
    int i = threadIdx.x;

    // Snapshot the confusion matrix, then reset it for the next launch/replay.
    if (i < NBINS) s_conf[i] = g_conf[i];
    __syncthreads();
    if (i < NBINS) g_conf[i] = 0u;

    float acc = 0.0f;
    if (i < NC) {
        float tp = (float)s_conf[i * NC + i];
        float rowsum = 0.0f, colsum = 0.0f;
        #pragma unroll
        for (int j = 0; j < NC; j++) {
            rowsum += (float)s_conf[i * NC + j];
            colsum += (float)s_conf[j * NC + i];
        }
        float fp = rowsum - tp;
        float fn = colsum - tp;
        float tn = (float)BHW - tp - fp - fn;
        float sens = (tp + 1.0f) / (tp + fn + 1.0f);
        float spec = (tn + 1.0f) / (tn + fp + 1.0f);
        acc = 0.5f * sens + 0.5f * spec;
    }
    if (i < 32) {   // classes 0..20 all live in warp 0
        #pragma unroll
        for (int off = 16; off > 0; off >>= 1)
            acc += __shfl_down_sync(0xffffffffu, acc, off);
        if (i == 0) out[0] = 1.0f - acc / (float)NC;
    }
}

extern "C" void kernel_launch(void* const* d_in, const int* in_sizes, int n_in,
                              void* d_out, int out_size) {
    const float* logits = (const float*)d_in[0];
    const int* target   = (const int*)d_in[1];
    float* out = (float*)d_out;

    hist_kernel<<<2048, 256>>>(logits, target);
    loss_kernel<<<1, 512>>>(out);
}